// round 3
// baseline (speedup 1.0000x reference)
#include <cuda_runtime.h>
#include <math.h>

#define B 8
#define S 2048
#define I_IN 8
#define H 256
#define NC 16       // CTAs per batch for recurrence
#define CHUNK 16    // h outputs per CTA (H/NC)
#define NT 256      // threads per block

// ---------------- scratch (static device globals; no runtime alloc) -------------
__device__ float g_hs0[(size_t)B * S * H];   // layer0 hidden states, 64MB
__device__ float g_hs1[(size_t)B * S * H];   // layer1 hidden states, 64MB
__device__ float g_hbuf0[2 * B * H];         // double-buffered h broadcast, layer0
__device__ float g_hbuf1[2 * B * H];         // layer1
__device__ unsigned int g_cnt0[B * 32];      // per-batch arrival counters (128B spaced)
__device__ unsigned int g_cnt1[B * 32];
__device__ float g_attnc[B * H];             // attention output (pre-wo), concat heads

__device__ __forceinline__ float sigmoidf_(float x) { return 1.f / (1.f + expf(-x)); }

// ---------------- init: reset counters + zero h(0) -----------------------------
__global__ void init_kernel() {
    int tid = blockIdx.x * blockDim.x + threadIdx.x;
    if (tid < 2 * B * H) { g_hbuf0[tid] = 0.f; g_hbuf1[tid] = 0.f; }
    if (tid < B * 32)    { g_cnt0[tid] = 0u;  g_cnt1[tid] = 0u; }
}

// ---------------- LSTM recurrence (persistent, cross-CTA sync per step) --------
// grid: (NC, B). CTA r of batch b owns h outputs [r*16, r*16+16) -> 64 gate rows.
// thread tid: segment s = tid>>6 (64-wide slice of the 256 dot), gate gL = tid&63.
// Weights held in registers for all 2048 steps.
template <int LAYER>
__global__ void __launch_bounds__(NT, 1) lstm_kernel(
    const float* __restrict__ xin,    // layer0: x [B,S,8]; layer1: unused (g_hs0)
    const float* __restrict__ w_ih,   // [1024, IN]
    const float* __restrict__ w_hh,   // [1024, 256]
    const float* __restrict__ b_ih,
    const float* __restrict__ b_hh)
{
    const int r   = blockIdx.x;
    const int b   = blockIdx.y;
    const int tid = threadIdx.x;
    const int s   = tid >> 6;     // 0..3, uniform within a warp
    const int gL  = tid & 63;     // 0..63
    const int q   = gL >> 4;      // gate type i/f/g/o
    const int j   = gL & 15;      // h index within chunk
    const int row = q * H + r * CHUNK + j;   // global gate row in [0,1024)

    constexpr int INW = LAYER ? 64 : 8;

    float whh[64];
#pragma unroll
    for (int k = 0; k < 64; k++) whh[k] = w_hh[row * H + s * 64 + k];

    float wih[INW];
#pragma unroll
    for (int k = 0; k < INW; k++) wih[k] = 0.f;
    if (LAYER) {
#pragma unroll
        for (int k = 0; k < 64; k++) wih[k] = w_ih[row * H + s * 64 + k];
    } else if (s == 0) {
#pragma unroll
        for (int k = 0; k < 8; k++) wih[k] = w_ih[row * 8 + k];
    }

    float bias_q[4];
    if (tid < CHUNK) {
#pragma unroll
        for (int qq = 0; qq < 4; qq++) {
            int rr = qq * H + r * CHUNK + tid;
            bias_q[qq] = b_ih[rr] + b_hh[rr];
        }
    }

    __shared__ float sh_h[H];
    __shared__ float sh_x[H];
    __shared__ float sh_part[4 * 64];

    float c = 0.f;   // cell state for h output (r*16 + tid), threads tid<16 only

    const float* xb = (LAYER ? (const float*)g_hs0 : xin)
                      + (size_t)b * S * (LAYER ? H : I_IN);
    float* hs_out = (LAYER ? g_hs1 : g_hs0) + (size_t)b * S * H;
    float* hb     = LAYER ? g_hbuf1 : g_hbuf0;
    float* hb_p0  = hb + b * H;
    float* hb_p1  = hb + B * H + b * H;
    unsigned int* cnt = (LAYER ? g_cnt1 : g_cnt0) + b * 32;

    for (int t = 0; t < S; t++) {
        // --- load h(t) broadcast (L2-coherent) + x(t) into SMEM ---
        const float* hr = (t & 1) ? hb_p1 : hb_p0;
        sh_h[tid] = __ldcg(&hr[tid]);
        if (LAYER) sh_x[tid] = xb[(size_t)t * H + tid];
        else if (tid < I_IN) sh_x[tid] = xb[t * I_IN + tid];
        __syncthreads();

        // --- partial gate dot (weights in regs, h broadcast from SMEM) ---
        float acc = 0.f;
#pragma unroll
        for (int k = 0; k < 64; k++) acc += whh[k] * sh_h[s * 64 + k];
        if (LAYER) {
#pragma unroll
            for (int k = 0; k < 64; k++) acc += wih[k] * sh_x[s * 64 + k];
        } else if (s == 0) {
#pragma unroll
            for (int k = 0; k < 8; k++) acc += wih[k] * sh_x[k];
        }
        sh_part[s * 64 + gL] = acc;
        __syncthreads();

        // --- reduce 4 segments, LSTM cell, publish h chunk ---
        if (tid < CHUNK) {
            float gate[4];
#pragma unroll
            for (int qq = 0; qq < 4; qq++) {
                int gg = qq * CHUNK + tid;
                gate[qq] = sh_part[gg] + sh_part[64 + gg] + sh_part[128 + gg]
                         + sh_part[192 + gg] + bias_q[qq];
            }
            float ig = sigmoidf_(gate[0]);
            float fg = sigmoidf_(gate[1]);
            float gv = tanhf(gate[2]);
            float og = sigmoidf_(gate[3]);
            c = fg * c + ig * gv;
            float hnew = og * tanhf(c);
            int hidx = r * CHUNK + tid;
            hs_out[(size_t)t * H + hidx] = hnew;
            float* hw = (t & 1) ? hb_p0 : hb_p1;   // write next parity
            __stcg(&hw[hidx], hnew);
        }

        // --- cross-CTA step barrier (release: fence+atomic; acquire: spin+fence) ---
        __threadfence();
        __syncthreads();
        if (tid == 0) {
            atomicAdd(cnt, 1u);
            const unsigned int target = (unsigned int)(t + 1) * NC;
            volatile unsigned int* vc = cnt;
            while (*vc < target) { }
        }
        __syncthreads();
        __threadfence();
    }
}

// ---------------- attention at the last query position --------------------------
// grid: B*HEADS CTAs. score_t = (qW . h1[b,t] + qb)/8 * 0.95^(S-1-t); softmax;
// attn = wv_head @ (sum_t p_t h1[b,t]) + bv_head.
__global__ void __launch_bounds__(NT, 1) attn_kernel(
    const float* __restrict__ wq, const float* __restrict__ bq,
    const float* __restrict__ wk, const float* __restrict__ bk,
    const float* __restrict__ wv, const float* __restrict__ bv)
{
    const int hd  = blockIdx.x & 3;
    const int b   = blockIdx.x >> 2;
    const int tid = threadIdx.x;
    const float* h1b = g_hs1 + (size_t)b * S * H;

    __shared__ float sh_last[H];
    __shared__ float sh_q[64];
    __shared__ float sh_qW[H];
    __shared__ float sh_qb;
    __shared__ float sc[S];       // 8KB
    __shared__ float red[NT];

    sh_last[tid] = h1b[(size_t)(S - 1) * H + tid];
    __syncthreads();

    if (tid < 64) {
        int rq = hd * 64 + tid;
        float a = bq[rq];
#pragma unroll 4
        for (int k = 0; k < H; k++) a += wq[rq * H + k] * sh_last[k];
        sh_q[tid] = a;
    }
    __syncthreads();
    {
        float a = 0.f;
#pragma unroll 4
        for (int d = 0; d < 64; d++) a += sh_q[d] * wk[(hd * 64 + d) * H + tid];
        sh_qW[tid] = a;
    }
    if (tid == 0) {
        float a = 0.f;
        for (int d = 0; d < 64; d++) a += sh_q[d] * bk[hd * 64 + d];
        sh_qb = a;
    }
    __syncthreads();

    const float L2D = -0.07400058144377693f;   // log2(0.95)
    const int warp = tid >> 5, lane = tid & 31;

    float qr[8];
#pragma unroll
    for (int k = 0; k < 8; k++) qr[k] = sh_qW[lane * 8 + k];

    for (int t = warp; t < S; t += 8) {
        const float4* hr4 = reinterpret_cast<const float4*>(h1b + (size_t)t * H);
        float4 h0v = hr4[lane * 2];
        float4 h1v = hr4[lane * 2 + 1];
        float a = qr[0]*h0v.x + qr[1]*h0v.y + qr[2]*h0v.z + qr[3]*h0v.w
                + qr[4]*h1v.x + qr[5]*h1v.y + qr[6]*h1v.z + qr[7]*h1v.w;
#pragma unroll
        for (int o = 16; o; o >>= 1) a += __shfl_xor_sync(0xffffffffu, a, o);
        if (lane == 0) {
            float sv = (a + sh_qb) * 0.125f;
            sc[t] = sv * exp2f((float)(S - 1 - t) * L2D);
        }
    }
    __syncthreads();

    // softmax over 2048
    float m = -1e30f;
    for (int i = tid; i < S; i += NT) m = fmaxf(m, sc[i]);
    red[tid] = m; __syncthreads();
    for (int o = NT / 2; o; o >>= 1) { if (tid < o) red[tid] = fmaxf(red[tid], red[tid + o]); __syncthreads(); }
    const float M = red[0];
    __syncthreads();
    float ssum = 0.f;
    for (int i = tid; i < S; i += NT) { float e = expf(sc[i] - M); sc[i] = e; ssum += e; }
    red[tid] = ssum; __syncthreads();
    for (int o = NT / 2; o; o >>= 1) { if (tid < o) red[tid] += red[tid + o]; __syncthreads(); }
    const float inv = 1.f / red[0];
    __syncthreads();

    // hbar[k] = inv * sum_t p_t * h1[b,t,k]  (coalesced column read)
    float a = 0.f;
#pragma unroll 8
    for (int t = 0; t < S; t++) a += sc[t] * h1b[(size_t)t * H + tid];
    a *= inv;
    __syncthreads();
    sh_last[tid] = a;          // reuse as hbar
    __syncthreads();

    if (tid < 64) {
        int rv = hd * 64 + tid;
        float o = bv[rv];
#pragma unroll 4
        for (int k = 0; k < H; k++) o += wv[rv * H + k] * sh_last[k];
        g_attnc[b * H + hd * 64 + tid] = o;
    }
}

// ---------------- output heads: context -> (mean, log_var) ----------------------
__global__ void __launch_bounds__(NT, 1) head_kernel(
    const float* __restrict__ wo, const float* __restrict__ bo,
    const float* __restrict__ wm, const float* __restrict__ bm,
    const float* __restrict__ wvr, const float* __restrict__ bvr,
    float* __restrict__ out)
{
    const int b = blockIdx.x;
    const int tid = threadIdx.x;
    __shared__ float sa[H], sctx[H];
    sa[tid] = g_attnc[b * H + tid];
    __syncthreads();
    float a = bo[tid];
#pragma unroll 4
    for (int k = 0; k < H; k++) a += wo[tid * H + k] * sa[k];
    sctx[tid] = a;
    __syncthreads();
    if (tid < 5) {
        float m = bm[tid], lv = bvr[tid];
        for (int k = 0; k < H; k++) {
            m  += wm[tid * H + k] * sctx[k];
            lv += wvr[tid * H + k] * sctx[k];
        }
        out[b * 5 + tid] = m;                 // mean  [B,5]
        out[B * 5 + b * 5 + tid] = lv;        // log_var [B,5]
    }
}

// ---------------- launch ---------------------------------------------------------
extern "C" void kernel_launch(void* const* d_in, const int* in_sizes, int n_in,
                              void* d_out, int out_size) {
    const float* x     = (const float*)d_in[0];
    const float* w_ih0 = (const float*)d_in[1];
    const float* w_hh0 = (const float*)d_in[2];
    const float* b_ih0 = (const float*)d_in[3];
    const float* b_hh0 = (const float*)d_in[4];
    const float* w_ih1 = (const float*)d_in[5];
    const float* w_hh1 = (const float*)d_in[6];
    const float* b_ih1 = (const float*)d_in[7];
    const float* b_hh1 = (const float*)d_in[8];
    const float* wq = (const float*)d_in[9];
    const float* bq = (const float*)d_in[10];
    const float* wk = (const float*)d_in[11];
    const float* bk = (const float*)d_in[12];
    const float* wv = (const float*)d_in[13];
    const float* bv = (const float*)d_in[14];
    const float* wo = (const float*)d_in[15];
    const float* bo = (const float*)d_in[16];
    const float* wm = (const float*)d_in[17];
    const float* bm = (const float*)d_in[18];
    const float* wvar = (const float*)d_in[19];
    const float* bvar = (const float*)d_in[20];
    float* out = (float*)d_out;

    init_kernel<<<16, 256>>>();

    dim3 grid_lstm(NC, B);   // 128 CTAs < 148 SMs: whole grid co-resident (safe spin-sync)
    lstm_kernel<0><<<grid_lstm, NT>>>(x, w_ih0, w_hh0, b_ih0, b_hh0);
    lstm_kernel<1><<<grid_lstm, NT>>>(x, w_ih1, w_hh1, b_ih1, b_hh1);

    attn_kernel<<<B * 4, NT>>>(wq, bq, wk, bk, wv, bv);
    head_kernel<<<B, NT>>>(wo, bo, wm, bm, wvar, bvar, out);
}

// round 4
// speedup vs baseline: 1.0471x; 1.0471x over previous
#include <cuda_runtime.h>
#include <math.h>
#include <stdint.h>

#define B 8
#define S 2048
#define I_IN 8
#define H 256
#define NC 16       // CTAs per cluster (= per batch)
#define CHUNK 16    // h outputs per CTA
#define NT 256
#define NSPLIT 8
#define SC (S / NSPLIT)   // 256

// ---------------- device scratch ----------------
__device__ float g_hs0[(size_t)B * S * H];
__device__ float g_hs1[(size_t)B * S * H];
__device__ float g_pm[B * 4 * NSPLIT];
__device__ float g_ps[B * 4 * NSPLIT];
__device__ float g_ph[B * 4 * NSPLIT * H];
__device__ float g_attnc[B * H];

__device__ __forceinline__ float sigmoidf_(float x) { return 1.f / (1.f + expf(-x)); }

// packed fp32x2 FMA (Blackwell)
__device__ __forceinline__ uint64_t fma2_(uint64_t a, uint64_t b, uint64_t c) {
    uint64_t d;
    asm("fma.rn.f32x2 %0, %1, %2, %3;" : "=l"(d) : "l"(a), "l"(b), "l"(c));
    return d;
}
__device__ __forceinline__ float hsum2_(uint64_t v) {
    return __uint_as_float((uint32_t)v) + __uint_as_float((uint32_t)(v >> 32));
}
__device__ __forceinline__ uint32_t smem_u32(const void* p) {
    uint32_t a;
    asm("{ .reg .u64 t; cvta.to.shared.u64 t, %1; cvt.u32.u64 %0, t; }" : "=r"(a) : "l"(p));
    return a;
}
__device__ __forceinline__ void st_remote(uint32_t laddr, uint32_t rank, float v) {
    asm volatile("{ .reg .b32 ra; mapa.shared::cluster.u32 ra, %0, %1; "
                 "st.shared::cluster.f32 [ra], %2; }"
                 :: "r"(laddr), "r"(rank), "f"(v) : "memory");
}
__device__ __forceinline__ void arrive_remote(uint32_t lmbar, uint32_t rank) {
    asm volatile("{ .reg .b32 ra; mapa.shared::cluster.u32 ra, %0, %1; "
                 "mbarrier.arrive.release.cluster.shared::cluster.b64 _, [ra]; }"
                 :: "r"(lmbar), "r"(rank) : "memory");
}
__device__ __forceinline__ void mbar_wait_cluster(uint32_t mbar, uint32_t parity) {
    uint32_t done;
    asm volatile("{ .reg .pred p; "
                 "mbarrier.try_wait.parity.acquire.cluster.shared::cta.b64 p, [%1], %2, 0x989680; "
                 "selp.b32 %0, 1, 0, p; }" : "=r"(done) : "r"(mbar), "r"(parity) : "memory");
    while (!done) {
        asm volatile("{ .reg .pred p; "
                     "mbarrier.try_wait.parity.acquire.cluster.shared::cta.b64 p, [%1], %2, 0x989680; "
                     "selp.b32 %0, 1, 0, p; }" : "=r"(done) : "r"(mbar), "r"(parity) : "memory");
    }
}
__device__ __forceinline__ void cluster_sync_() {
    asm volatile("barrier.cluster.arrive.aligned;" ::: "memory");
    asm volatile("barrier.cluster.wait.aligned;" ::: "memory");
}

// ---------------- LSTM: 16-CTA cluster per batch, DSMEM h broadcast -------------
template <int LAYER>
__global__ void __launch_bounds__(NT, 1) __cluster_dims__(NC, 1, 1)
lstm_kernel(const float* __restrict__ xin,
            const float* __restrict__ w_ih, const float* __restrict__ w_hh,
            const float* __restrict__ b_ih, const float* __restrict__ b_hh)
{
    const int r   = blockIdx.x;        // rank within cluster
    const int b   = blockIdx.y;        // batch
    const int tid = threadIdx.x;
    const int s   = tid >> 6;          // 64-wide segment of the 256-dot
    const int gL  = tid & 63;          // local gate row
    const int q   = gL >> 4;           // gate type i/f/g/o
    const int j   = gL & 15;
    const int row = q * H + r * CHUNK + j;

    __shared__ alignas(16) float sh_h[2][H];   // double-buffered h(t); remote-written
    __shared__ alignas(16) float sh_x[H];
    __shared__ float sh_part[4 * 64];
    __shared__ float sh_act[64];
    __shared__ float sh_hnew[CHUNK];
    __shared__ alignas(8) uint64_t sh_mbar;

    // ---- register-resident packed weights ----
    uint64_t whh2[32];
    {
        const uint64_t* w64 = reinterpret_cast<const uint64_t*>(w_hh) + ((row * H + s * 64) >> 1);
#pragma unroll
        for (int k = 0; k < 32; k++) whh2[k] = w64[k];
    }
    constexpr int NW = LAYER ? 32 : 4;
    uint64_t wih2[NW];
    if (LAYER) {
        const uint64_t* w64 = reinterpret_cast<const uint64_t*>(w_ih) + ((row * H + s * 64) >> 1);
#pragma unroll
        for (int k = 0; k < NW; k++) wih2[k] = w64[k];
    } else {
        const uint64_t* w64 = reinterpret_cast<const uint64_t*>(w_ih) + ((row * I_IN) >> 1);
#pragma unroll
        for (int k = 0; k < NW; k++) wih2[k] = (s == 0) ? w64[k] : 0ull;
    }
    const float bias = b_ih[row] + b_hh[row];   // used by tid<64 only

    // ---- init smem + mbarrier; cluster-wide ready barrier ----
    const uint32_t mbar_a = smem_u32(&sh_mbar);
    if (tid == 0)
        asm volatile("mbarrier.init.shared.b64 [%0], %1;" :: "r"(mbar_a), "r"(NC * CHUNK) : "memory");
    sh_h[0][tid] = 0.f; sh_h[1][tid] = 0.f; sh_x[tid] = 0.f;
    __syncthreads();
    cluster_sync_();

    const float* xb = LAYER ? (g_hs0 + (size_t)b * S * H) : (xin + (size_t)b * S * I_IN);
    float* hs_out   = (LAYER ? g_hs1 : g_hs0) + (size_t)b * S * H;

    // push-slot addresses: value v = tid&15 of MY chunk -> peer (tid>>4)
    const uint32_t peer = tid >> 4;
    const uint32_t hb_addr[2] = { smem_u32(&sh_h[0][r * CHUNK + (tid & 15)]),
                                  smem_u32(&sh_h[1][r * CHUNK + (tid & 15)]) };

    float xreg = 0.f;
    if (LAYER) xreg = __ldg(xb + tid);
    else if (tid < I_IN) xreg = xb[tid];

    float c = 0.f;   // cell state (owners tid<16)

    for (int t = 0; t < S; t++) {
        // stage x(t), prefetch x(t+1)
        if (LAYER) {
            sh_x[tid] = xreg;
            int tn = (t + 1 < S) ? t + 1 : t;
            xreg = __ldg(xb + (size_t)tn * H + tid);
        } else if (tid < I_IN) {
            sh_x[tid] = xreg;
            int tn = (t + 1 < S) ? t + 1 : t;
            xreg = xb[tn * I_IN + tid];
        }
        if (t > 0) mbar_wait_cluster(mbar_a, (t - 1) & 1);
        __syncthreads();

        // partial gate dot (packed f32x2, 2 acc chains)
        const uint64_t* h64 = reinterpret_cast<const uint64_t*>(&sh_h[t & 1][s * 64]);
        uint64_t a0 = 0, a1 = 0;
#pragma unroll
        for (int k = 0; k < 16; k++) a0 = fma2_(whh2[k], h64[k], a0);
#pragma unroll
        for (int k = 16; k < 32; k++) a1 = fma2_(whh2[k], h64[k], a1);
        if (LAYER) {
            const uint64_t* x64 = reinterpret_cast<const uint64_t*>(&sh_x[s * 64]);
#pragma unroll
            for (int k = 0; k < 16; k++) a0 = fma2_(wih2[k], x64[k], a0);
#pragma unroll
            for (int k = 16; k < 32; k++) a1 = fma2_(wih2[k], x64[k], a1);
        } else if (s == 0) {
            const uint64_t* x64 = reinterpret_cast<const uint64_t*>(sh_x);
#pragma unroll
            for (int k = 0; k < 4; k++) a0 = fma2_(wih2[k], x64[k], a0);
        }
        sh_part[s * 64 + gL] = hsum2_(a0) + hsum2_(a1);
        __syncthreads();

        // parallel activations: one gate per thread (tid<64)
        if (tid < 64) {
            float g = sh_part[tid] + sh_part[64 + tid] + sh_part[128 + tid]
                    + sh_part[192 + tid] + bias;
            sh_act[tid] = (q == 2) ? tanhf(g) : sigmoidf_(g);
        }
        __syncthreads();

        // cell update (owners tid<16)
        if (tid < CHUNK) {
            float ig = sh_act[tid], fg = sh_act[16 + tid];
            float gv = sh_act[32 + tid], og = sh_act[48 + tid];
            c = fg * c + ig * gv;
            float hnew = og * tanhf(c);
            sh_hnew[tid] = hnew;
            hs_out[(size_t)t * H + r * CHUNK + tid] = hnew;
        }
        __syncthreads();

        // push h(t+1) chunk to every cluster CTA + arrive on its mbarrier
        if (t + 1 < S) {
            float v = sh_hnew[tid & 15];
            st_remote(hb_addr[(t + 1) & 1], peer, v);
            arrive_remote(mbar_a, peer);
        }
    }
    cluster_sync_();
}

// ---------------- attention partials: split-S, split-softmax ---------------------
__global__ void __launch_bounds__(NT, 1) attn_part_kernel(
    const float* __restrict__ wq, const float* __restrict__ bq,
    const float* __restrict__ wk, const float* __restrict__ bk)
{
    const int cidx = blockIdx.x;          // split 0..7
    const int bh   = blockIdx.y;          // b*4+hd
    const int b = bh >> 2, hd = bh & 3;
    const int tid = threadIdx.x;
    const float* h1b = g_hs1 + (size_t)b * S * H;
    const int base = cidx * SC;

    __shared__ float sh_last[H];
    __shared__ float sh_q[64];
    __shared__ float sh_qW[H];
    __shared__ float sh_qb;
    __shared__ float sc[SC];
    __shared__ float red[NT];

    sh_last[tid] = h1b[(size_t)(S - 1) * H + tid];
    __syncthreads();
    if (tid < 64) {
        int rq = hd * 64 + tid;
        float a = bq[rq];
#pragma unroll 4
        for (int k = 0; k < H; k++) a += wq[rq * H + k] * sh_last[k];
        sh_q[tid] = a;
    }
    __syncthreads();
    {
        float a = 0.f;
#pragma unroll 4
        for (int d = 0; d < 64; d++) a += sh_q[d] * wk[(hd * 64 + d) * H + tid];
        sh_qW[tid] = a;
    }
    if (tid == 0) {
        float a = 0.f;
        for (int d = 0; d < 64; d++) a += sh_q[d] * bk[hd * 64 + d];
        sh_qb = a;
    }
    __syncthreads();

    const float L2D = -0.07400058144377693f;   // log2(0.95)
    const int warp = tid >> 5, lane = tid & 31;
    float qr[8];
#pragma unroll
    for (int k = 0; k < 8; k++) qr[k] = sh_qW[lane * 8 + k];

#pragma unroll 2
    for (int i = warp; i < SC; i += 8) {
        int t = base + i;
        const float4* hr4 = reinterpret_cast<const float4*>(h1b + (size_t)t * H);
        float4 h0v = hr4[lane * 2], h1v = hr4[lane * 2 + 1];
        float a = qr[0]*h0v.x + qr[1]*h0v.y + qr[2]*h0v.z + qr[3]*h0v.w
                + qr[4]*h1v.x + qr[5]*h1v.y + qr[6]*h1v.z + qr[7]*h1v.w;
#pragma unroll
        for (int o = 16; o; o >>= 1) a += __shfl_xor_sync(0xffffffffu, a, o);
        if (lane == 0)
            sc[i] = (a + sh_qb) * 0.125f * exp2f((float)(S - 1 - t) * L2D);
    }
    __syncthreads();

    // split softmax (SC == NT)
    red[tid] = sc[tid]; __syncthreads();
    for (int o = NT / 2; o; o >>= 1) { if (tid < o) red[tid] = fmaxf(red[tid], red[tid + o]); __syncthreads(); }
    const float M = red[0]; __syncthreads();
    float e = expf(sc[tid] - M);
    sc[tid] = e;
    red[tid] = e; __syncthreads();
    for (int o = NT / 2; o; o >>= 1) { if (tid < o) red[tid] += red[tid + o]; __syncthreads(); }
    const float SUM = red[0];
    __syncthreads();

    // partial weighted h sum (coalesced)
    float acc = 0.f;
#pragma unroll 8
    for (int i = 0; i < SC; i++) acc += sc[i] * h1b[(size_t)(base + i) * H + tid];
    g_ph[(size_t)(bh * NSPLIT + cidx) * H + tid] = acc;
    if (tid == 0) { g_pm[bh * NSPLIT + cidx] = M; g_ps[bh * NSPLIT + cidx] = SUM; }
}

// ---------------- combine splits + V projection ----------------------------------
__global__ void __launch_bounds__(NT, 1) attn_combine_kernel(
    const float* __restrict__ wv, const float* __restrict__ bv)
{
    const int bh = blockIdx.x;
    const int b = bh >> 2, hd = bh & 3;
    const int tid = threadIdx.x;
    __shared__ float sh_w[NSPLIT];
    __shared__ float sh_hbar[H];
    __shared__ float sh_inv;
    if (tid == 0) {
        float M = -1e30f;
        for (int cI = 0; cI < NSPLIT; cI++) M = fmaxf(M, g_pm[bh * NSPLIT + cI]);
        float tot = 0.f;
        for (int cI = 0; cI < NSPLIT; cI++) {
            float w = expf(g_pm[bh * NSPLIT + cI] - M);
            sh_w[cI] = w;
            tot += w * g_ps[bh * NSPLIT + cI];
        }
        sh_inv = 1.f / tot;
    }
    __syncthreads();
    float a = 0.f;
#pragma unroll
    for (int cI = 0; cI < NSPLIT; cI++) a += sh_w[cI] * g_ph[(size_t)(bh * NSPLIT + cI) * H + tid];
    sh_hbar[tid] = a * sh_inv;
    __syncthreads();
    if (tid < 64) {
        int rv = hd * 64 + tid;
        float o = bv[rv];
#pragma unroll 4
        for (int k = 0; k < H; k++) o += wv[rv * H + k] * sh_hbar[k];
        g_attnc[b * H + hd * 64 + tid] = o;
    }
}

// ---------------- output heads ----------------------------------------------------
__global__ void __launch_bounds__(NT, 1) head_kernel(
    const float* __restrict__ wo, const float* __restrict__ bo,
    const float* __restrict__ wm, const float* __restrict__ bm,
    const float* __restrict__ wvr, const float* __restrict__ bvr,
    float* __restrict__ out)
{
    const int b = blockIdx.x;
    const int tid = threadIdx.x;
    __shared__ float sa[H], sctx[H];
    sa[tid] = g_attnc[b * H + tid];
    __syncthreads();
    float a = bo[tid];
#pragma unroll 4
    for (int k = 0; k < H; k++) a += wo[tid * H + k] * sa[k];
    sctx[tid] = a;
    __syncthreads();
    if (tid < 5) {
        float m = bm[tid], lv = bvr[tid];
        for (int k = 0; k < H; k++) {
            m  += wm[tid * H + k] * sctx[k];
            lv += wvr[tid * H + k] * sctx[k];
        }
        out[b * 5 + tid] = m;
        out[B * 5 + b * 5 + tid] = lv;
    }
}

// ---------------- launch ----------------------------------------------------------
extern "C" void kernel_launch(void* const* d_in, const int* in_sizes, int n_in,
                              void* d_out, int out_size) {
    const float* x     = (const float*)d_in[0];
    const float* w_ih0 = (const float*)d_in[1];
    const float* w_hh0 = (const float*)d_in[2];
    const float* b_ih0 = (const float*)d_in[3];
    const float* b_hh0 = (const float*)d_in[4];
    const float* w_ih1 = (const float*)d_in[5];
    const float* w_hh1 = (const float*)d_in[6];
    const float* b_ih1 = (const float*)d_in[7];
    const float* b_hh1 = (const float*)d_in[8];
    const float* wq = (const float*)d_in[9];
    const float* bq = (const float*)d_in[10];
    const float* wk = (const float*)d_in[11];
    const float* bk = (const float*)d_in[12];
    const float* wv = (const float*)d_in[13];
    const float* bv = (const float*)d_in[14];
    const float* wo = (const float*)d_in[15];
    const float* bo = (const float*)d_in[16];
    const float* wm = (const float*)d_in[17];
    const float* bm = (const float*)d_in[18];
    const float* wvar = (const float*)d_in[19];
    const float* bvar = (const float*)d_in[20];
    float* out = (float*)d_out;

    // cluster size 16 > portable 8: opt in (idempotent; no allocation)
    cudaFuncSetAttribute(lstm_kernel<0>, cudaFuncAttributeNonPortableClusterSizeAllowed, 1);
    cudaFuncSetAttribute(lstm_kernel<1>, cudaFuncAttributeNonPortableClusterSizeAllowed, 1);

    dim3 grid_lstm(NC, B);   // 8 clusters of 16 CTAs; sync is intra-cluster only
    lstm_kernel<0><<<grid_lstm, NT>>>(x, w_ih0, w_hh0, b_ih0, b_hh0);
    lstm_kernel<1><<<grid_lstm, NT>>>(nullptr, w_ih1, w_hh1, b_ih1, b_hh1);

    attn_part_kernel<<<dim3(NSPLIT, B * 4), NT>>>(wq, bq, wk, bk);
    attn_combine_kernel<<<B * 4, NT>>>(wv, bv);
    head_kernel<<<B, NT>>>(wo, bo, wm, bm, wvar, bvar, out);
}